// round 14
// baseline (speedup 1.0000x reference)
#include <cuda_runtime.h>
#include <cuda_fp16.h>
#include <math.h>

// Problem constants
#define H     1536
#define H3    4608          // 3*H
#define HV    128           // vocab
#define ML    128           // max_length
#define AROWS 129           // ML+1 attention rows
#define MPAD  132           // padded row stride for 129-wide matrices
#define GRID  148
#define BLOCK 1024

// ---------------- device scratch (no allocations allowed) ----------------
__device__ __align__(16) float g_encout[AROWS * H];   // encoder_outputs
__device__ __align__(16) float g_gi[2][H3];           // Wih-side gates (+bih), ping-pong
__device__ __align__(16) float g_gh[2][H3];           // Whh-side gates (+bhh), ping-pong
__device__ __align__(16) float g_attnh[AROWS];        // attn h-half logits
__device__ __align__(16) float g_o[HV];               // output logits
__device__ __align__(16) float g_x[H];                // relu(comb) input to dec GRU
__device__ __align__(16) float g_M[H * MPAD];         // comb_W_ctx @ encout^T  (write-once)
__device__ __align__(16) float g_attE[HV * MPAD];     // attn emb-half table (write-once)
__device__ __align__(16) float g_combE[HV * H];       // comb emb-half table (write-once)
__device__ unsigned g_bar;                            // grid barrier (monotonic)

// fp16 weight copies (converted in-kernel before first barrier; deterministic)
__device__ __align__(16) __half g_eWih_h[(size_t)H3 * H];
__device__ __align__(16) __half g_eWhh_h[(size_t)H3 * H];
__device__ __align__(16) __half g_dWih_h[(size_t)H3 * H];
__device__ __align__(16) __half g_dWhh_h[(size_t)H3 * H];
__device__ __align__(16) __half g_outW_h[HV * H];
__device__ __align__(16) __half g_attnWh_h[AROWS * H];   // attn_W h-half

// ---- grid barrier: release-add / acquire-poll (no CCTL.IVALL L1 flush) ----
// Sound: every mutable cross-phase global READ uses __ldcg (L2-direct);
// write-once tables + in-kernel-converted weights are only cold-read per SM
// (stores don't populate L1; L1 flushed at launch start) so .ca is safe.
__device__ __forceinline__ void grid_sync() {
    __syncthreads();
    if (threadIdx.x == 0) {
        unsigned* p = &g_bar;
        unsigned old;
        asm volatile("atom.release.gpu.global.add.u32 %0, [%1], %2;"
                     : "=r"(old) : "l"(p), "r"(1u) : "memory");
        unsigned target = old - (old % GRID) + GRID;
        unsigned v;
        for (;;) {
            asm volatile("ld.acquire.gpu.global.u32 %0, [%1];"
                         : "=r"(v) : "l"(p) : "memory");
            if ((int)(v - target) >= 0) break;
            __nanosleep(32);
        }
    }
    __syncthreads();
}

// ---------------- warp helpers ----------------
__device__ __forceinline__ float wredu(float v) {
#pragma unroll
    for (int o = 16; o; o >>= 1) v += __shfl_xor_sync(0xffffffffu, v, o);
    return v;
}

// argmax with first-index tie-break (matches jnp.argmax)
__device__ __forceinline__ void wargmax(float& m, int& am) {
#pragma unroll
    for (int o = 16; o; o >>= 1) {
        float m2 = __shfl_xor_sync(0xffffffffu, m, o);
        int   a2 = __shfl_xor_sync(0xffffffffu, am, o);
        if (m2 > m || (m2 == m && a2 < am)) { m = m2; am = a2; }
    }
}

__device__ __forceinline__ float sigm(float x) { return 1.f / (1.f + expf(-x)); }

// 8 fp16 weights (one uint4) against 8 fp32 vector elems; register-safe casts
__device__ __forceinline__ float acc8(uint4 A, float4 b0, float4 b1, float s) {
    __half2 h0 = *reinterpret_cast<const __half2*>(&A.x);
    __half2 h1 = *reinterpret_cast<const __half2*>(&A.y);
    __half2 h2 = *reinterpret_cast<const __half2*>(&A.z);
    __half2 h3 = *reinterpret_cast<const __half2*>(&A.w);
    float2 f;
    f = __half22float2(h0); s = fmaf(f.x, b0.x, s); s = fmaf(f.y, b0.y, s);
    f = __half22float2(h1); s = fmaf(f.x, b0.z, s); s = fmaf(f.y, b0.w, s);
    f = __half22float2(h2); s = fmaf(f.x, b1.x, s); s = fmaf(f.y, b1.y, s);
    f = __half22float2(h3); s = fmaf(f.x, b1.z, s); s = fmaf(f.y, b1.w, s);
    return s;
}

// fp16 weight row (global) . fp32 vector (SMEM-staged)
__device__ __forceinline__ float dot1536h(const __half* __restrict__ w,
                                          const float4* __restrict__ sx, int lane) {
    const uint4* w8 = (const uint4*)w;
    float s = 0.f;
#pragma unroll
    for (int i = 0; i < 6; i++) {
        int idx = lane + 32 * i;
        s = acc8(w8[idx], sx[2 * idx], sx[2 * idx + 1], s);
    }
    return s;
}

// fp32: 4 dots sharing one weight row (untiled precompute GEMMs)
__device__ __forceinline__ void dot1536x4(const float* __restrict__ w,
                                          const float* __restrict__ x0,
                                          const float* __restrict__ x1,
                                          const float* __restrict__ x2,
                                          const float* __restrict__ x3,
                                          int lane, float* r) {
    const float4* w4 = (const float4*)w;
    const float4* a0 = (const float4*)x0;
    const float4* a1 = (const float4*)x1;
    const float4* a2 = (const float4*)x2;
    const float4* a3 = (const float4*)x3;
    float s0 = 0.f, s1 = 0.f, s2 = 0.f, s3 = 0.f;
#pragma unroll 4
    for (int i = 0; i < 12; i++) {
        float4 a = w4[lane + 32 * i];
        float4 b;
        b = a0[lane + 32 * i];
        s0 = fmaf(a.x, b.x, s0); s0 = fmaf(a.y, b.y, s0);
        s0 = fmaf(a.z, b.z, s0); s0 = fmaf(a.w, b.w, s0);
        b = a1[lane + 32 * i];
        s1 = fmaf(a.x, b.x, s1); s1 = fmaf(a.y, b.y, s1);
        s1 = fmaf(a.z, b.z, s1); s1 = fmaf(a.w, b.w, s1);
        b = a2[lane + 32 * i];
        s2 = fmaf(a.x, b.x, s2); s2 = fmaf(a.y, b.y, s2);
        s2 = fmaf(a.z, b.z, s2); s2 = fmaf(a.w, b.w, s2);
        b = a3[lane + 32 * i];
        s3 = fmaf(a.x, b.x, s3); s3 = fmaf(a.y, b.y, s3);
        s3 = fmaf(a.z, b.z, s3); s3 = fmaf(a.w, b.w, s3);
    }
    r[0] = s0; r[1] = s1; r[2] = s2; r[3] = s3;
}

__device__ __forceinline__ void cvt_range(const float4* __restrict__ src,
                                          __half2* __restrict__ dst,
                                          int n4, int gt, int NT) {
    for (int i = gt; i < n4; i += NT) {
        float4 v = src[i];
        dst[2 * i]     = __floats2half2_rn(v.x, v.y);
        dst[2 * i + 1] = __floats2half2_rn(v.z, v.w);
    }
}

// ---------------- persistent kernel ----------------
__global__ __launch_bounds__(BLOCK, 1)
void seq2seq_kernel(const int* __restrict__ input, int L,
                    const float* __restrict__ emb_enc,
                    const float* __restrict__ enc_Wih, const float* __restrict__ enc_Whh,
                    const float* __restrict__ enc_bih, const float* __restrict__ enc_bhh,
                    const float* __restrict__ emb_dec,
                    const float* __restrict__ attn_W, const float* __restrict__ attn_b,
                    const float* __restrict__ comb_W, const float* __restrict__ comb_b,
                    const float* __restrict__ dec_Wih, const float* __restrict__ dec_Whh,
                    const float* __restrict__ dec_bih, const float* __restrict__ dec_bhh,
                    const float* __restrict__ out_W, const float* __restrict__ out_b,
                    float* __restrict__ out, int write_tok)
{
    const int tid  = threadIdx.x;
    const int lane = tid & 31;
    const int wid  = tid >> 5;
    const int b    = blockIdx.x;
    const int WGID = wid * GRID + b;
    const int NW   = GRID * (BLOCK >> 5);

    __shared__ __align__(16) float s_h[H];   // hidden state (block-local, redundant)
    __shared__ __align__(16) float s_x[H];   // staged emb / x vector
    __shared__ float s_w[AROWS];             // unnormalized softmax weights
    __shared__ float s_red[32];
    __shared__ float s_S, s_lse;
    __shared__ int   s_tok;
    float4* s_h4 = (float4*)s_h;
    float4* s_x4 = (float4*)s_x;

    // ---- prologue: fp16 conversion + init (all before first barrier) ----
    {
        int gt = b * BLOCK + tid;
        int NT = GRID * BLOCK;
        const int n4 = H3 * H / 4;
        cvt_range((const float4*)enc_Wih, (__half2*)g_eWih_h, n4, gt, NT);
        cvt_range((const float4*)enc_Whh, (__half2*)g_eWhh_h, n4, gt, NT);
        cvt_range((const float4*)dec_Wih, (__half2*)g_dWih_h, n4, gt, NT);
        cvt_range((const float4*)dec_Whh, (__half2*)g_dWhh_h, n4, gt, NT);
        cvt_range((const float4*)out_W,   (__half2*)g_outW_h, HV * H / 4, gt, NT);
        {   // attn_W h-half (row stride 2H, offset H)
            __half2* dst = (__half2*)g_attnWh_h;
            for (int i = gt; i < AROWS * H / 4; i += NT) {
                int k = (i * 4) / H, c = (i * 4) % H;
                const float4 v = *(const float4*)(attn_W + k * (2 * H) + H + c);
                dst[2 * i]     = __floats2half2_rn(v.x, v.y);
                dst[2 * i + 1] = __floats2half2_rn(v.z, v.w);
            }
        }
        for (int i = L * H + gt; i < AROWS * H; i += NT) g_encout[i] = 0.f;
        for (int i = tid; i < H; i += BLOCK) s_h[i] = 0.f;   // h0 (block-local)
    }

    // ---- P_E (untiled): emb-half GEMMs for attn and comb + bias fold ----
    {
        int r0 = b * 11 + min(b, 37);
        int nr = 11 + (b < 37 ? 1 : 0);       // 1665 virtual rows total
        for (int u = wid; u < nr * 32; u += 32) {
            int lr = u >> 5;
            int vc = (u & 31) << 2;           // vocab chunk base (0..124)
            int r  = r0 + lr;
            const float* w; float bias;
            if (r < AROWS) { w = attn_W + r * (2 * H); bias = attn_b[r]; }
            else           { w = comb_W + (r - AROWS) * (2 * H); bias = comb_b[r - AROWS]; }
            float s[4];
            dot1536x4(w, emb_dec + vc * H, emb_dec + (vc + 1) * H,
                         emb_dec + (vc + 2) * H, emb_dec + (vc + 3) * H, lane, s);
#pragma unroll
            for (int q = 0; q < 4; q++) s[q] = wredu(s[q]);
            if (lane == 0) {
#pragma unroll
                for (int q = 0; q < 4; q++) {
                    if (r < AROWS) g_attE[(vc + q) * MPAD + r] = s[q] + bias;
                    else           g_combE[(vc + q) * H + (r - AROWS)] = s[q] + bias;
                }
            }
        }
    }
    grid_sync();

    // =========================== ENCODER ===========================
    // step t: [combine(t-1) + stage emb] -> 9216 single-dot tasks -> barrier
    for (int t = 0; t < L; t++) {
        if (t > 0) {
            const int p2 = (t - 1) & 1;
            for (int i = tid; i < H; i += BLOCK) {
                float r  = sigm(__ldcg(&g_gi[p2][i])         + __ldcg(&g_gh[p2][i]));
                float z  = sigm(__ldcg(&g_gi[p2][H + i])     + __ldcg(&g_gh[p2][H + i]));
                float n  = tanhf(__ldcg(&g_gi[p2][2 * H + i]) + r * __ldcg(&g_gh[p2][2 * H + i]));
                float hv = (1.f - z) * n + z * s_h[i];
                s_h[i] = hv;
                if (b == 0) g_encout[(t - 1) * H + i] = hv;
            }
        }
        {
            int tk = __ldg(&input[t]);
            const float4* e4 = (const float4*)(emb_enc + tk * H);
            if (tid < 384) s_x4[tid] = __ldg(e4 + tid);
        }
        __syncthreads();

        const int p = t & 1;
        for (int u = WGID; u < 2 * H3; u += NW) {       // ~2 tasks/warp
            if (u < H3) {
                float s = wredu(dot1536h(g_eWih_h + (size_t)u * H, s_x4, lane));
                if (lane == 0) g_gi[p][u] = s + enc_bih[u];
            } else {
                int j = u - H3;
                float s = wredu(dot1536h(g_eWhh_h + (size_t)j * H, s_h4, lane));
                if (lane == 0) g_gh[p][j] = s + enc_bhh[j];
            }
        }
        grid_sync();
    }
    // final combine -> h_L (+ encout[L-1] by block0)
    {
        const int p2 = (L - 1) & 1;
        for (int i = tid; i < H; i += BLOCK) {
            float r  = sigm(__ldcg(&g_gi[p2][i])         + __ldcg(&g_gh[p2][i]));
            float z  = sigm(__ldcg(&g_gi[p2][H + i])     + __ldcg(&g_gh[p2][H + i]));
            float n  = tanhf(__ldcg(&g_gi[p2][2 * H + i]) + r * __ldcg(&g_gh[p2][2 * H + i]));
            float hv = (1.f - z) * n + z * s_h[i];
            s_h[i] = hv;
            if (b == 0) g_encout[(L - 1) * H + i] = hv;
        }
        __syncthreads();
    }
    grid_sync();   // publish block0's encout rows

    // ---- P_M (untiled): M[i][k] = comb_W_ctx[i,:] . encout[k,:] ----
    {
        int r0 = b * 10 + min(b, 56);
        int nr = 10 + (b < 56 ? 1 : 0);       // 1536 rows total
        for (int u = wid; u < nr * 33; u += 32) {
            int lr = u / 33;
            int kc = (u % 33) * 4;            // 0..128
            int i  = r0 + lr;
            const float* w = comb_W + i * (2 * H) + H;
            int k0 = min(kc,     AROWS - 1);
            int k1 = min(kc + 1, AROWS - 1);
            int k2 = min(kc + 2, AROWS - 1);
            int k3 = min(kc + 3, AROWS - 1);
            float s[4];
            dot1536x4(w, g_encout + k0 * H, g_encout + k1 * H,
                         g_encout + k2 * H, g_encout + k3 * H, lane, s);
#pragma unroll
            for (int q = 0; q < 4; q++) s[q] = wredu(s[q]);
            if (lane == 0) {
#pragma unroll
                for (int q = 0; q < 4; q++) {
                    int k = kc + q;
                    if (k < AROWS) g_M[i * MPAD + k] = s[q];
                }
            }
        }
    }
    grid_sync();

    // =========================== DECODER ===========================
    for (int t = 0; t < ML; t++) {
        const int p = t & 1;

        // --- P1: combine h (t>0), then 4736 single-dot tasks + coop attn rows ---
        if (t > 0) {
            const int p2 = (t - 1) & 1;
            for (int i = tid; i < H; i += BLOCK) {
                float r = sigm(__ldcg(&g_gi[p2][i])         + __ldcg(&g_gh[p2][i]));
                float z = sigm(__ldcg(&g_gi[p2][H + i])     + __ldcg(&g_gh[p2][H + i]));
                float n = tanhf(__ldcg(&g_gi[p2][2 * H + i]) + r * __ldcg(&g_gh[p2][2 * H + i]));
                s_h[i] = (1.f - z) * n + z * s_h[i];
            }
        }
        __syncthreads();
        {
            int task = WGID;                  // exactly 4736 tasks: 1 per warp
            if (task < H3) {
                float s = wredu(dot1536h(g_dWhh_h + (size_t)task * H, s_h4, lane));
                if (lane == 0) g_gh[p][task] = s + dec_bhh[task];
            } else {
                int v = task - H3;            // 0..127
                float s = wredu(dot1536h(g_outW_h + v * H, s_h4, lane));
                if (lane == 0) g_o[v] = s + out_b[v];
            }
            if (b < AROWS) {                  // block-cooperative attn_h row b
                float pp = 0.f;
                if (tid < 768) {
                    __half2 hw = ((const __half2*)(g_attnWh_h + b * H))[tid];
                    float2 fw = __half22float2(hw);
                    float2 hv = ((const float2*)s_h)[tid];
                    pp = fw.x * hv.x + fw.y * hv.y;
                }
                pp = wredu(pp);
                if (lane == 0) s_red[wid] = pp;
                __syncthreads();
                if (wid == 0) {
                    float v2 = s_red[lane];
                    v2 = wredu(v2);
                    if (lane == 0) g_attnh[b] = v2;
                }
            }
        }
        grid_sync();

        // --- P2: token select, emit row t-1, softmax, x rows ---
        if (wid == 0) {
            int tok; float lse;
            if (t == 0) { tok = 0; lse = 0.f; }
            else {
                float m = -1e30f; int am = HV;
                for (int v = lane; v < HV; v += 32) {
                    float ov = __ldcg(&g_o[v]);
                    if (ov > m) { m = ov; am = v; }
                }
                wargmax(m, am);
                float e = 0.f;
                for (int v = lane; v < HV; v += 32) e += expf(__ldcg(&g_o[v]) - m);
                e = wredu(e);
                lse = m + logf(e);
                tok = am;
            }
            if (lane == 0) { s_tok = tok; s_lse = lse; }
        }
        __syncthreads();
        const int tok = s_tok;
        if (t > 0 && b == 0 && wid == 1) {
            for (int v = lane; v < HV; v += 32) out[(t - 1) * HV + v] = __ldcg(&g_o[v]) - s_lse;
            if (lane == 0 && write_tok) out[ML * HV + (t - 1)] = (float)tok;
        }
        if (wid == 0) {
            const float* aE = g_attE + tok * MPAD;   // write-once: .ca safe
            float m = -1e30f;
            for (int k = lane; k < AROWS; k += 32) m = fmaxf(m, aE[k] + __ldcg(&g_attnh[k]));
#pragma unroll
            for (int o = 16; o; o >>= 1) m = fmaxf(m, __shfl_xor_sync(0xffffffffu, m, o));
            float ssum = 0.f;
            for (int k = lane; k < AROWS; k += 32) {
                float e = expf(aE[k] + __ldcg(&g_attnh[k]) - m);
                s_w[k] = e;
                ssum += e;
            }
            ssum = wredu(ssum);
            if (lane == 0) s_S = ssum;
        }
        __syncthreads();
        {
            const float invS = 1.f / s_S;
            const float* cE = g_combE + tok * H;     // write-once: .ca safe
            for (int i = WGID; i < H; i += NW) {
                const float* Mr = g_M + i * MPAD;    // write-once: .ca safe
                float s = 0.f;
                for (int k = lane; k < AROWS; k += 32) s = fmaf(s_w[k], Mr[k], s);
                s = wredu(s);
                if (lane == 0) g_x[i] = fmaxf(0.f, cE[i] + s * invS);
            }
        }
        grid_sync();

        // --- P3: stage x; 4608 single-dot tasks -> g_gi ---
        {
            if (tid < 384) s_x4[tid] = __ldcg(((const float4*)g_x) + tid);
            __syncthreads();
            int j = WGID;
            if (j < H3) {
                float s = wredu(dot1536h(g_dWih_h + (size_t)j * H, s_x4, lane));
                if (lane == 0) g_gi[p][j] = s + dec_bih[j];
            }
        }
        grid_sync();
    }

    // ---- epilogue: final combine + last logits row ----
    {
        const int p2 = (ML - 1) & 1;
        for (int i = tid; i < H; i += BLOCK) {
            float r = sigm(__ldcg(&g_gi[p2][i])         + __ldcg(&g_gh[p2][i]));
            float z = sigm(__ldcg(&g_gi[p2][H + i])     + __ldcg(&g_gh[p2][H + i]));
            float n = tanhf(__ldcg(&g_gi[p2][2 * H + i]) + r * __ldcg(&g_gh[p2][2 * H + i]));
            s_h[i] = (1.f - z) * n + z * s_h[i];
        }
        __syncthreads();
        int v = WGID;
        if (v < HV) {
            float s = wredu(dot1536h(g_outW_h + v * H, s_h4, lane));
            if (lane == 0) g_o[v] = s + out_b[v];
        }
    }
    grid_sync();

    if (b == 0 && wid == 0) {
        float m = -1e30f; int am = HV;
        for (int v = lane; v < HV; v += 32) {
            float ov = __ldcg(&g_o[v]);
            if (ov > m) { m = ov; am = v; }
        }
        wargmax(m, am);
        float e = 0.f;
        for (int v = lane; v < HV; v += 32) e += expf(__ldcg(&g_o[v]) - m);
        e = wredu(e);
        float lse = m + logf(e);
        for (int v = lane; v < HV; v += 32) out[(ML - 1) * HV + v] = __ldcg(&g_o[v]) - lse;
        if (lane == 0 && write_tok) out[ML * HV + (ML - 1)] = (float)am;
    }
}

// ---------------- launch ----------------
extern "C" void kernel_launch(void* const* d_in, const int* in_sizes, int n_in,
                              void* d_out, int out_size) {
    const int*   input   = (const int*)  d_in[0];
    const int    L       = in_sizes[0];
    // d_in[1] = max_length scalar (compile-time ML=128)
    const float* emb_enc = (const float*)d_in[2];
    const float* enc_Wih = (const float*)d_in[3];
    const float* enc_Whh = (const float*)d_in[4];
    const float* enc_bih = (const float*)d_in[5];
    const float* enc_bhh = (const float*)d_in[6];
    const float* emb_dec = (const float*)d_in[7];
    const float* attn_W  = (const float*)d_in[8];
    const float* attn_b  = (const float*)d_in[9];
    const float* comb_W  = (const float*)d_in[10];
    const float* comb_b  = (const float*)d_in[11];
    const float* dec_Wih = (const float*)d_in[12];
    const float* dec_Whh = (const float*)d_in[13];
    const float* dec_bih = (const float*)d_in[14];
    const float* dec_bhh = (const float*)d_in[15];
    const float* out_W   = (const float*)d_in[16];
    const float* out_b   = (const float*)d_in[17];

    int write_tok = (out_size >= ML * HV + ML) ? 1 : 0;

    seq2seq_kernel<<<GRID, BLOCK>>>(input, L, emb_enc,
                                    enc_Wih, enc_Whh, enc_bih, enc_bhh,
                                    emb_dec, attn_W, attn_b, comb_W, comb_b,
                                    dec_Wih, dec_Whh, dec_bih, dec_bhh,
                                    out_W, out_b,
                                    (float*)d_out, write_tok);
}